// round 13
// baseline (speedup 1.0000x reference)
#include <cuda_runtime.h>
#include <cuda_bf16.h>
#include <math.h>
#include <stdint.h>

#define Bb   16
#define Nn   256
#define Ff   128
#define Hh   8
#define DHh  16
#define Ll   9
#define BNn  4096
#define Emax 65536

// ---------------- scratch (device globals; no allocations) ----------------
__device__ float g_m[Bb*Nn*Nn];
__device__ float g_r[Bb*Nn*Nn];
__device__ float g_deg[BNn];
__device__ float g_dis[BNn];
__device__ float g_out[BNn*Ff];
__device__ float g_h[BNn*Ff];
__device__ float g_q[BNn*Ff];
__device__ float g_k[BNn*Ff];
__device__ float g_v[BNn*Ff];
__device__ float g_o[BNn*Ff];
__device__ float g_x[BNn*Ff];
__device__ float g_f1[BNn*2*Ff];
// packed bf16 transposed B panels for MCL (ping-pong)
__device__ uint32_t g_bth0[Bb*Nn*128];
__device__ uint32_t g_btl0[Bb*Nn*128];
__device__ uint32_t g_bth1[Bb*Nn*128];
__device__ uint32_t g_btl1[Bb*Nn*128];
// CSR by col
__device__ int g_cnt[BNn];
__device__ int g_off[BNn+1];
__device__ int g_cur[BNn];
__device__ int g_elist[Emax];

__device__ __forceinline__ float warpsum(float v){
#pragma unroll
    for(int o=16;o;o>>=1) v += __shfl_xor_sync(0xffffffffu, v, o);
    return v;
}

__device__ __forceinline__ float gelu_exact(float x){
    return 0.5f*x*(1.0f + erff(x*0.70710678118654752f));
}

// ---------------- packed f32x2 helpers (Blackwell FFMA2) ----------------
__device__ __forceinline__ unsigned long long pack2(float lo, float hi){
    unsigned long long r; asm("mov.b64 %0, {%1,%2};" : "=l"(r) : "f"(lo), "f"(hi)); return r;
}
__device__ __forceinline__ void unpack2(unsigned long long v, float& lo, float& hi){
    asm("mov.b64 {%0,%1}, %2;" : "=f"(lo), "=f"(hi) : "l"(v));
}
__device__ __forceinline__ unsigned long long fma2(unsigned long long a, unsigned long long b, unsigned long long c){
    unsigned long long d; asm("fma.rn.f32x2 %0, %1, %2, %3;" : "=l"(d) : "l"(a), "l"(b), "l"(c)); return d;
}
__device__ __forceinline__ unsigned long long mul2(unsigned long long a, unsigned long long b){
    unsigned long long d; asm("mul.rn.f32x2 %0, %1, %2;" : "=l"(d) : "l"(a), "l"(b)); return d;
}

// ---------------- bf16x3 tensor-core GEMM machinery ----------------
__device__ __forceinline__ void splitb(float x, float y, uint32_t& hi, uint32_t& lo){
    __nv_bfloat16 hx = __float2bfloat16_rn(x);
    __nv_bfloat16 hy = __float2bfloat16_rn(y);
    float lx = x - __bfloat162float(hx);
    float ly = y - __bfloat162float(hy);
    __nv_bfloat16 lxh = __float2bfloat16_rn(lx);
    __nv_bfloat16 lyh = __float2bfloat16_rn(ly);
    hi = ((uint32_t)__bfloat16_as_ushort(hy)<<16) | (uint32_t)__bfloat16_as_ushort(hx);
    lo = ((uint32_t)__bfloat16_as_ushort(lyh)<<16) | (uint32_t)__bfloat16_as_ushort(lxh);
}
__device__ __forceinline__ int swz(int r, int k){
    return ((r>>1)<<5) + ((r&1)<<4) + (k ^ (((r>>1)&3)<<2));
}
__device__ __forceinline__ void mma_bf16(float* c, uint32_t a0,uint32_t a1,uint32_t a2,uint32_t a3,
                                         uint32_t b0,uint32_t b1){
    asm volatile("mma.sync.aligned.m16n8k16.row.col.f32.bf16.bf16.f32 "
        "{%0,%1,%2,%3},{%4,%5,%6,%7},{%8,%9},{%0,%1,%2,%3};\n"
        : "+f"(c[0]),"+f"(c[1]),"+f"(c[2]),"+f"(c[3])
        : "r"(a0),"r"(a1),"r"(a2),"r"(a3),"r"(b0),"r"(b1));
}

// C[64x64 tile] = act(alpha * A[M,K] @ W[Nc,K]^T + bias).  128 threads, 4 warps of 32x32.
template<int ACT>
__device__ __forceinline__ void gemm_tc_tile(const float* __restrict__ A, const float* __restrict__ W,
        const float* __restrict__ bias, float* __restrict__ C,
        int Nc, int K, float alpha, int bx, int by)
{
    __shared__ __align__(16) uint32_t As[2][64*16];
    __shared__ __align__(16) uint32_t Ws[2][64*16];
    int tid = threadIdx.x;
    int wid = tid>>5, lane = tid&31, gid = lane>>2, tig = lane&3;
    int wm = (wid&1)*32, wn = (wid>>1)*32;
    int row0 = by*64, col0 = bx*64;
    int lr = tid>>2;
    int lk8 = (tid&3)*8;
    int lw  = (tid&3)*4;

    float acc[2][4][4];
#pragma unroll
    for(int i=0;i<2;i++)
#pragma unroll
    for(int j=0;j<4;j++)
#pragma unroll
    for(int t=0;t<4;t++) acc[i][j][t]=0.f;

    const float* Ap = A + (size_t)(row0+lr)*K + lk8;
    const float* Wp = W + (size_t)(col0+lr)*K + lk8;
    float4 pa0a = *(const float4*)(Ap);
    float4 pa0b = *(const float4*)(Ap+4);
    float4 pa1a = *(const float4*)(Ap + (size_t)32*K);
    float4 pa1b = *(const float4*)(Ap + (size_t)32*K + 4);
    float4 pw0a = *(const float4*)(Wp);
    float4 pw0b = *(const float4*)(Wp+4);
    float4 pw1a = *(const float4*)(Wp + (size_t)32*K);
    float4 pw1b = *(const float4*)(Wp + (size_t)32*K + 4);

    for(int k0=0;k0<K;k0+=32){
        uint4 h, l;
        splitb(pa0a.x,pa0a.y,h.x,l.x); splitb(pa0a.z,pa0a.w,h.y,l.y);
        splitb(pa0b.x,pa0b.y,h.z,l.z); splitb(pa0b.z,pa0b.w,h.w,l.w);
        *(uint4*)&As[0][swz(lr,lw)] = h;  *(uint4*)&As[1][swz(lr,lw)] = l;
        splitb(pa1a.x,pa1a.y,h.x,l.x); splitb(pa1a.z,pa1a.w,h.y,l.y);
        splitb(pa1b.x,pa1b.y,h.z,l.z); splitb(pa1b.z,pa1b.w,h.w,l.w);
        *(uint4*)&As[0][swz(lr+32,lw)] = h;  *(uint4*)&As[1][swz(lr+32,lw)] = l;
        splitb(pw0a.x,pw0a.y,h.x,l.x); splitb(pw0a.z,pw0a.w,h.y,l.y);
        splitb(pw0b.x,pw0b.y,h.z,l.z); splitb(pw0b.z,pw0b.w,h.w,l.w);
        *(uint4*)&Ws[0][swz(lr,lw)] = h;  *(uint4*)&Ws[1][swz(lr,lw)] = l;
        splitb(pw1a.x,pw1a.y,h.x,l.x); splitb(pw1a.z,pw1a.w,h.y,l.y);
        splitb(pw1b.x,pw1b.y,h.z,l.z); splitb(pw1b.z,pw1b.w,h.w,l.w);
        *(uint4*)&Ws[0][swz(lr+32,lw)] = h;  *(uint4*)&Ws[1][swz(lr+32,lw)] = l;
        __syncthreads();

        if(k0+32<K){
            pa0a = *(const float4*)(Ap + k0+32);
            pa0b = *(const float4*)(Ap + k0+36);
            pa1a = *(const float4*)(Ap + (size_t)32*K + k0+32);
            pa1b = *(const float4*)(Ap + (size_t)32*K + k0+36);
            pw0a = *(const float4*)(Wp + k0+32);
            pw0b = *(const float4*)(Wp + k0+36);
            pw1a = *(const float4*)(Wp + (size_t)32*K + k0+32);
            pw1b = *(const float4*)(Wp + (size_t)32*K + k0+36);
        }

#pragma unroll
        for(int s=0;s<2;s++){
            int ks = s*8 + tig;
            uint32_t afh[2][4], afl[2][4], bfh[4][2], bfl[4][2];
#pragma unroll
            for(int i=0;i<2;i++){
                int r = wm + 16*i + gid;
                afh[i][0]=As[0][swz(r,  ks)];   afl[i][0]=As[1][swz(r,  ks)];
                afh[i][1]=As[0][swz(r+8,ks)];   afl[i][1]=As[1][swz(r+8,ks)];
                afh[i][2]=As[0][swz(r,  ks+4)]; afl[i][2]=As[1][swz(r,  ks+4)];
                afh[i][3]=As[0][swz(r+8,ks+4)]; afl[i][3]=As[1][swz(r+8,ks+4)];
            }
#pragma unroll
            for(int j=0;j<4;j++){
                int n = wn + 8*j + gid;
                bfh[j][0]=Ws[0][swz(n,ks)];     bfl[j][0]=Ws[1][swz(n,ks)];
                bfh[j][1]=Ws[0][swz(n,ks+4)];   bfl[j][1]=Ws[1][swz(n,ks+4)];
            }
#pragma unroll
            for(int i=0;i<2;i++)
#pragma unroll
            for(int j=0;j<4;j++){
                mma_bf16(acc[i][j], afl[i][0],afl[i][1],afl[i][2],afl[i][3], bfh[j][0],bfh[j][1]);
                mma_bf16(acc[i][j], afh[i][0],afh[i][1],afh[i][2],afh[i][3], bfl[j][0],bfl[j][1]);
                mma_bf16(acc[i][j], afh[i][0],afh[i][1],afh[i][2],afh[i][3], bfh[j][0],bfh[j][1]);
            }
        }
        __syncthreads();
    }

#pragma unroll
    for(int i=0;i<2;i++){
        int rg = row0 + wm + 16*i + gid;
#pragma unroll
        for(int j=0;j<4;j++){
            int cg = col0 + wn + 8*j + tig*2;
            float b0v = bias ? bias[cg]   : 0.f;
            float b1v = bias ? bias[cg+1] : 0.f;
            float v0 = acc[i][j][0]*alpha + b0v;
            float v1 = acc[i][j][1]*alpha + b1v;
            float v2 = acc[i][j][2]*alpha + b0v;
            float v3 = acc[i][j][3]*alpha + b1v;
            if(ACT==1){ v0=gelu_exact(v0); v1=gelu_exact(v1); v2=gelu_exact(v2); v3=gelu_exact(v3); }
            *(float2*)&C[(size_t)rg*Nc + cg]     = make_float2(v0,v1);
            *(float2*)&C[(size_t)(rg+8)*Nc + cg] = make_float2(v2,v3);
        }
    }
}

template<int ACT>
__global__ void __launch_bounds__(128) k_gemm_tc(const float* __restrict__ A, const float* __restrict__ W,
        const float* __restrict__ bias, float* __restrict__ C, int Nc, int K, float alpha){
    gemm_tc_tile<ACT>(A, W, bias, C, Nc, K, alpha, blockIdx.x, blockIdx.y);
}

__global__ void __launch_bounds__(128) k_qkv_tc(const float* __restrict__ A,
        const float* __restrict__ qw, const float* __restrict__ kw, const float* __restrict__ vw){
    const float* W; float* C; float alpha;
    if(blockIdx.z==0){ W=qw; C=g_q; alpha=0.25f; }
    else if(blockIdx.z==1){ W=kw; C=g_k; alpha=1.f; }
    else { W=vw; C=g_v; alpha=1.f; }
    gemm_tc_tile<0>(A, W, nullptr, C, Ff, Ff, alpha, blockIdx.x, blockIdx.y);
}

// -------- fused GEMM(+bias) + residual + LayerNorm ----------
__global__ void __launch_bounds__(128) k_gemm_ln(const float* __restrict__ A, const float* __restrict__ W,
        const float* __restrict__ bias, const float* __restrict__ res,
        const float* __restrict__ gg, const float* __restrict__ gb,
        float* __restrict__ out, int K)
{
    __shared__ __align__(16) uint32_t As[2][32*16];
    __shared__ __align__(16) uint32_t Ws[2][128*16];
    __shared__ float Cs[32][132];
    int tid = threadIdx.x;
    int wid = tid>>5, lane = tid&31, gid = lane>>2, tig = lane&3;
    int wn = wid*32;
    int row0 = blockIdx.x*32;
    int lr = tid>>2;
    int lk8 = (tid&3)*8;
    int lw  = (tid&3)*4;

    float acc[2][4][4];
#pragma unroll
    for(int i=0;i<2;i++)
#pragma unroll
    for(int j=0;j<4;j++)
#pragma unroll
    for(int t=0;t<4;t++) acc[i][j][t]=0.f;

    const float* Ap = A + (size_t)(row0+lr)*K + lk8;
    const float* Wp = W + (size_t)lr*K + lk8;
    float4 paa = *(const float4*)(Ap);
    float4 pab = *(const float4*)(Ap+4);
    float4 pwa[4], pwb[4];
#pragma unroll
    for(int p=0;p<4;p++){
        pwa[p] = *(const float4*)(Wp + (size_t)32*p*K);
        pwb[p] = *(const float4*)(Wp + (size_t)32*p*K + 4);
    }

    for(int k0=0;k0<K;k0+=32){
        uint4 h, l;
        splitb(paa.x,paa.y,h.x,l.x); splitb(paa.z,paa.w,h.y,l.y);
        splitb(pab.x,pab.y,h.z,l.z); splitb(pab.z,pab.w,h.w,l.w);
        *(uint4*)&As[0][swz(lr,lw)] = h;  *(uint4*)&As[1][swz(lr,lw)] = l;
#pragma unroll
        for(int p=0;p<4;p++){
            splitb(pwa[p].x,pwa[p].y,h.x,l.x); splitb(pwa[p].z,pwa[p].w,h.y,l.y);
            splitb(pwb[p].x,pwb[p].y,h.z,l.z); splitb(pwb[p].z,pwb[p].w,h.w,l.w);
            *(uint4*)&Ws[0][swz(lr+32*p,lw)] = h;  *(uint4*)&Ws[1][swz(lr+32*p,lw)] = l;
        }
        __syncthreads();

        if(k0+32<K){
            paa = *(const float4*)(Ap + k0+32);
            pab = *(const float4*)(Ap + k0+36);
#pragma unroll
            for(int p=0;p<4;p++){
                pwa[p] = *(const float4*)(Wp + (size_t)32*p*K + k0+32);
                pwb[p] = *(const float4*)(Wp + (size_t)32*p*K + k0+36);
            }
        }

#pragma unroll
        for(int s=0;s<2;s++){
            int ks = s*8 + tig;
            uint32_t afh[2][4], afl[2][4];
#pragma unroll
            for(int i=0;i<2;i++){
                int r = 16*i + gid;
                afh[i][0]=As[0][swz(r,  ks)];   afl[i][0]=As[1][swz(r,  ks)];
                afh[i][1]=As[0][swz(r+8,ks)];   afl[i][1]=As[1][swz(r+8,ks)];
                afh[i][2]=As[0][swz(r,  ks+4)]; afl[i][2]=As[1][swz(r,  ks+4)];
                afh[i][3]=As[0][swz(r+8,ks+4)]; afl[i][3]=As[1][swz(r+8,ks+4)];
            }
#pragma unroll
            for(int j=0;j<4;j++){
                int n = wn + 8*j + gid;
                uint32_t b0h=Ws[0][swz(n,ks)],   b0l=Ws[1][swz(n,ks)];
                uint32_t b1h=Ws[0][swz(n,ks+4)], b1l=Ws[1][swz(n,ks+4)];
#pragma unroll
                for(int i=0;i<2;i++){
                    mma_bf16(acc[i][j], afl[i][0],afl[i][1],afl[i][2],afl[i][3], b0h,b1h);
                    mma_bf16(acc[i][j], afh[i][0],afh[i][1],afh[i][2],afh[i][3], b0l,b1l);
                    mma_bf16(acc[i][j], afh[i][0],afh[i][1],afh[i][2],afh[i][3], b0h,b1h);
                }
            }
        }
        __syncthreads();
    }

#pragma unroll
    for(int i=0;i<2;i++){
        int rg = 16*i + gid;
#pragma unroll
        for(int j=0;j<4;j++){
            int cg = wn + 8*j + tig*2;
            float b0v = bias[cg], b1v = bias[cg+1];
            *(float2*)&Cs[rg][cg]   = make_float2(acc[i][j][0]+b0v, acc[i][j][1]+b1v);
            *(float2*)&Cs[rg+8][cg] = make_float2(acc[i][j][2]+b0v, acc[i][j][3]+b1v);
        }
    }
    __syncthreads();

    int r = tid>>2, part = tid&3;
    const float* resp = res + (size_t)(row0+r)*Ff + part*32;
    float v[32]; float s=0.f;
#pragma unroll
    for(int i=0;i<8;i++){
        float4 rv = *(const float4*)(resp + i*4);
        float* cp = &Cs[r][part*32 + i*4];
        v[i*4+0]=cp[0]+rv.x; v[i*4+1]=cp[1]+rv.y; v[i*4+2]=cp[2]+rv.z; v[i*4+3]=cp[3]+rv.w;
        s += v[i*4+0]+v[i*4+1]+v[i*4+2]+v[i*4+3];
    }
    s += __shfl_xor_sync(0xffffffffu, s, 1);
    s += __shfl_xor_sync(0xffffffffu, s, 2);
    float mean = s * (1.f/Ff);
    float vv=0.f;
#pragma unroll
    for(int i=0;i<32;i++){ float d=v[i]-mean; vv += d*d; }
    vv += __shfl_xor_sync(0xffffffffu, vv, 1);
    vv += __shfl_xor_sync(0xffffffffu, vv, 2);
    float inv = rsqrtf(vv*(1.f/Ff) + 1e-5f);
    float* op = out + (size_t)(row0+r)*Ff + part*32;
#pragma unroll
    for(int i=0;i<8;i++){
        int c = part*32 + i*4;
        float4 o;
        o.x=(v[i*4+0]-mean)*inv*gg[c]   + gb[c];
        o.y=(v[i*4+1]-mean)*inv*gg[c+1] + gb[c+1];
        o.z=(v[i*4+2]-mean)*inv*gg[c+2] + gb[c+2];
        o.w=(v[i*4+3]-mean)*inv*gg[c+3] + gb[c+3];
        *(float4*)(op + i*4) = o;
    }
}

// ---- prep: split normalized m into packed transposed bf16 panels (seed for MCL iter 0) ----
// grid (8, Bb), 256 threads.  Block handles rows [row0,row0+32) of m.
__global__ void __launch_bounds__(256) k_prep_b(const float* __restrict__ src,
        uint32_t* __restrict__ bth, uint32_t* __restrict__ btl){
    int bb = blockIdx.y;
    int row0 = blockIdx.x*32;
    __shared__ float Cs[32][260];
    int tid = threadIdx.x;
#pragma unroll
    for(int i=0;i<8;i++){
        int idx = tid + i*256;          // float4 index 0..2047
        int r = idx>>6, c = (idx&63)*4;
        *(float4*)&Cs[r][c] = *(const float4*)(src + (size_t)(bb*Nn+row0+r)*Nn + c);
    }
    __syncthreads();
    int n = tid;
    size_t base = ((size_t)bb*Nn + n)*128 + row0/2;
#pragma unroll
    for(int q=0;q<4;q++){
        uint4 h, l;
        splitb(Cs[q*8+0][n], Cs[q*8+1][n], h.x, l.x);
        splitb(Cs[q*8+2][n], Cs[q*8+3][n], h.y, l.y);
        splitb(Cs[q*8+4][n], Cs[q*8+5][n], h.z, l.z);
        splitb(Cs[q*8+6][n], Cs[q*8+7][n], h.w, l.w);
        *(uint4*)&bth[base + q*4] = h;
        *(uint4*)&btl[base + q*4] = l;
    }
}

// ---- MCL step: D = rownorm( A @ B [, ^6] );  B from packed panels, writes next B panels ----
// 256 threads = 8 warps (32x32).  tile 32 rows x 256 cols, grid (8, Bb).
__global__ void __launch_bounds__(256) k_bmm_rn(const float* __restrict__ A,
        const uint32_t* __restrict__ bth, const uint32_t* __restrict__ btl,
        uint32_t* __restrict__ oth, uint32_t* __restrict__ otl,
        float* __restrict__ Dfin, int pow6){
    int bb = blockIdx.y;
    const float* Ab = A + (size_t)bb*Nn*Nn;

    __shared__ __align__(16) uint32_t SM[2*32*16 + 2*256*16];   // 36KB; Cs aliased
    uint32_t (*As)[32*16]  = (uint32_t(*)[32*16])SM;
    uint32_t (*Bs)[256*16] = (uint32_t(*)[256*16])(SM + 2*32*16);
    float (*Cs)[260] = (float(*)[260])SM;

    int tid = threadIdx.x;
    int wid = tid>>5, lane = tid&31, gid = lane>>2, tig = lane&3;
    int wn = wid*32;
    int row0 = blockIdx.x*32;
    int lr4 = tid>>3;          // A row
    int lk4 = (tid&7)*4;       // A float col offset
    int lkw = (tid&7)*2;       // A word col offset

    float acc[2][4][4];
#pragma unroll
    for(int i=0;i<2;i++)
#pragma unroll
    for(int j=0;j<4;j++)
#pragma unroll
    for(int t=0;t<4;t++) acc[i][j][t]=0.f;

    const uint32_t* bhp = bth + ((size_t)bb*Nn + tid)*128;
    const uint32_t* blp = btl + ((size_t)bb*Nn + tid)*128;

    // prefetch chunk 0
    float4 pa = *(const float4*)(Ab + (size_t)(row0+lr4)*Nn + lk4);
    uint4 ph[4], pl[4];
#pragma unroll
    for(int q=0;q<4;q++){
        ph[q] = *(const uint4*)&bhp[q*4];
        pl[q] = *(const uint4*)&blp[q*4];
    }

    for(int k0=0;k0<Nn;k0+=32){
        {
            uint32_t h0,l0,h1,l1;
            splitb(pa.x,pa.y,h0,l0); splitb(pa.z,pa.w,h1,l1);
            uint2 hh; hh.x=h0; hh.y=h1;
            uint2 ll; ll.x=l0; ll.y=l1;
            *(uint2*)&As[0][swz(lr4,lkw)] = hh;
            *(uint2*)&As[1][swz(lr4,lkw)] = ll;
        }
#pragma unroll
        for(int q=0;q<4;q++){
            *(uint4*)&Bs[0][swz(tid, q*4)] = ph[q];
            *(uint4*)&Bs[1][swz(tid, q*4)] = pl[q];
        }
        __syncthreads();

        if(k0+32<Nn){
            pa = *(const float4*)(Ab + (size_t)(row0+lr4)*Nn + k0+32+lk4);
            int wb = (k0+32)>>1;
#pragma unroll
            for(int q=0;q<4;q++){
                ph[q] = *(const uint4*)&bhp[wb + q*4];
                pl[q] = *(const uint4*)&blp[wb + q*4];
            }
        }

#pragma unroll
        for(int s=0;s<2;s++){
            int ks = s*8 + tig;
            uint32_t afh[2][4], afl[2][4];
#pragma unroll
            for(int i=0;i<2;i++){
                int r = 16*i + gid;
                afh[i][0]=As[0][swz(r,  ks)];   afl[i][0]=As[1][swz(r,  ks)];
                afh[i][1]=As[0][swz(r+8,ks)];   afl[i][1]=As[1][swz(r+8,ks)];
                afh[i][2]=As[0][swz(r,  ks+4)]; afl[i][2]=As[1][swz(r,  ks+4)];
                afh[i][3]=As[0][swz(r+8,ks+4)]; afl[i][3]=As[1][swz(r+8,ks+4)];
            }
#pragma unroll
            for(int j=0;j<4;j++){
                int n = wn + 8*j + gid;
                uint32_t b0h=Bs[0][swz(n,ks)],   b0l=Bs[1][swz(n,ks)];
                uint32_t b1h=Bs[0][swz(n,ks+4)], b1l=Bs[1][swz(n,ks+4)];
#pragma unroll
                for(int i=0;i<2;i++){
                    mma_bf16(acc[i][j], afl[i][0],afl[i][1],afl[i][2],afl[i][3], b0h,b1h);
                    mma_bf16(acc[i][j], afh[i][0],afh[i][1],afh[i][2],afh[i][3], b0l,b1l);
                    mma_bf16(acc[i][j], afh[i][0],afh[i][1],afh[i][2],afh[i][3], b0h,b1h);
                }
            }
        }
        __syncthreads();
    }

    // write acc into Cs (aliases As/Bs; all smem reads complete)
#pragma unroll
    for(int i=0;i<2;i++){
        int rg = 16*i + gid;
#pragma unroll
        for(int j=0;j<4;j++){
            int cg = wn + 8*j + tig*2;
            *(float2*)&Cs[rg][cg]   = make_float2(acc[i][j][0], acc[i][j][1]);
            *(float2*)&Cs[rg+8][cg] = make_float2(acc[i][j][2], acc[i][j][3]);
        }
    }
    __syncthreads();

    // rownorm (with optional ^6), write normalized values back to Cs
    {
        int r = tid>>3, part = tid&7;
        float s = 0.f;
        float vals[32];
#pragma unroll
        for(int i=0;i<8;i++){
            float4 c = *(const float4*)&Cs[r][part*4 + i*32];
            if(pow6){
                float t;
                t=c.x*c.x; c.x=t*t*t;  t=c.y*c.y; c.y=t*t*t;
                t=c.z*c.z; c.z=t*t*t;  t=c.w*c.w; c.w=t*t*t;
            }
            vals[i*4+0]=c.x; vals[i*4+1]=c.y; vals[i*4+2]=c.z; vals[i*4+3]=c.w;
            s += c.x+c.y+c.z+c.w;
        }
        s += __shfl_xor_sync(0xffffffffu, s, 1);
        s += __shfl_xor_sync(0xffffffffu, s, 2);
        s += __shfl_xor_sync(0xffffffffu, s, 4);
        float inv = 1.0f/(s + 1e-6f);
#pragma unroll
        for(int i=0;i<8;i++){
            float4 c;
            c.x=vals[i*4+0]*inv; c.y=vals[i*4+1]*inv;
            c.z=vals[i*4+2]*inv; c.w=vals[i*4+3]*inv;
            *(float4*)&Cs[r][part*4 + i*32] = c;
        }
    }
    __syncthreads();

    // write packed transposed panels for next iteration (and f32 D on final iter)
    {
        int n = tid;
        size_t base = ((size_t)bb*Nn + n)*128 + row0/2;
#pragma unroll
        for(int q=0;q<4;q++){
            uint4 h, l;
            splitb(Cs[q*8+0][n], Cs[q*8+1][n], h.x, l.x);
            splitb(Cs[q*8+2][n], Cs[q*8+3][n], h.y, l.y);
            splitb(Cs[q*8+4][n], Cs[q*8+5][n], h.z, l.z);
            splitb(Cs[q*8+6][n], Cs[q*8+7][n], h.w, l.w);
            *(uint4*)&oth[base + q*4] = h;
            *(uint4*)&otl[base + q*4] = l;
        }
        if(Dfin){
#pragma unroll
            for(int r=0;r<32;r++)
                Dfin[(size_t)(bb*Nn+row0+r)*Nn + n] = Cs[r][n];
        }
    }
}

// ---------------- setup kernels ----------------
__global__ void k_init_m(const int* __restrict__ n_counts){
    int i = blockIdx.x*blockDim.x + threadIdx.x;
    if(i >= Bb*Nn*Nn) return;
    int b = i / (Nn*Nn);
    int rc = i % (Nn*Nn);
    int r = rc / Nn, c = rc % Nn;
    g_m[i] = (r==c && r < n_counts[b]) ? 1.0f : 0.0f;
}

__global__ void k_build_adj(const int* __restrict__ ei, int E){
    int e = blockIdx.x*blockDim.x + threadIdx.x;
    if(e>=E) return;
    int row = ei[e], col = ei[E+e];
    int eb = row/Nn, es = row%Nn, et = col%Nn;
    g_m[(eb*Nn+es)*Nn + et] = 1.0f;
}

__global__ void k_rownorm(const float* __restrict__ src, float* __restrict__ dst, int pow6){
    int warp = threadIdx.x>>5, lane = threadIdx.x&31;
    int row = blockIdx.x*8 + warp;
    const float* sp = src + (size_t)row*Nn + lane*8;
    float4 a = *(const float4*)(sp);
    float4 b = *(const float4*)(sp+4);
    if(pow6){
        float t;
        t=a.x*a.x; a.x=t*t*t;  t=a.y*a.y; a.y=t*t*t;
        t=a.z*a.z; a.z=t*t*t;  t=a.w*a.w; a.w=t*t*t;
        t=b.x*b.x; b.x=t*t*t;  t=b.y*b.y; b.y=t*t*t;
        t=b.z*b.z; b.z=t*t*t;  t=b.w*b.w; b.w=t*t*t;
    }
    float s = a.x+a.y+a.z+a.w + b.x+b.y+b.z+b.w;
    s = warpsum(s);
    float inv = 1.0f/(s + 1e-6f);
    a.x*=inv; a.y*=inv; a.z*=inv; a.w*=inv;
    b.x*=inv; b.y*=inv; b.z*=inv; b.w*=inv;
    float* dp = dst + (size_t)row*Nn + lane*8;
    *(float4*)(dp)   = a;
    *(float4*)(dp+4) = b;
}

__global__ void k_zero2(){
    int i = blockIdx.x*blockDim.x + threadIdx.x;
    if(i<BNn){ g_deg[i]=0.f; g_cnt[i]=0; }
}
__global__ void k_edge_cnt(const int* __restrict__ ei, int E){
    int e = blockIdx.x*blockDim.x + threadIdx.x;
    if(e>=E) return;
    atomicAdd(&g_deg[ei[e]], 1.0f);
    atomicAdd(&g_cnt[ei[E+e]], 1);
}

__global__ void k_csr_scan(){
    __shared__ int wsum[32];
    int tid = threadIdx.x;
    int base = tid*4;
    int v0=g_cnt[base], v1=g_cnt[base+1], v2=g_cnt[base+2], v3=g_cnt[base+3];
    int sum = v0+v1+v2+v3;
    int lane = tid&31, wid = tid>>5;
    int x = sum;
#pragma unroll
    for(int o=1;o<32;o<<=1){ int y=__shfl_up_sync(0xffffffffu,x,o); if(lane>=o) x+=y; }
    if(lane==31) wsum[wid]=x;
    __syncthreads();
    if(wid==0){
        int t = wsum[lane];
#pragma unroll
        for(int o=1;o<32;o<<=1){ int y=__shfl_up_sync(0xffffffffu,t,o); if(lane>=o) t+=y; }
        wsum[lane]=t;
    }
    __syncthreads();
    int excl = x - sum + (wid ? wsum[wid-1] : 0);
    int run = excl;
    g_off[base]=run;   g_cur[base]=run;   run+=v0;
    g_off[base+1]=run; g_cur[base+1]=run; run+=v1;
    g_off[base+2]=run; g_cur[base+2]=run; run+=v2;
    g_off[base+3]=run; g_cur[base+3]=run; run+=v3;
    if(tid==1023) g_off[BNn]=run;
#pragma unroll
    for(int j=0;j<4;j++) g_dis[base+j] = rsqrtf(g_deg[base+j] + 1.0f);
}
__global__ void k_csr_scatter(const int* __restrict__ ei, int E){
    int e = blockIdx.x*blockDim.x + threadIdx.x;
    if(e>=E) return;
    int pos = atomicAdd(&g_cur[ei[E+e]], 1);
    g_elist[pos] = e;
}

// ---------------- fused GCN: gather (CSR, 4-edge batched) + node update + LN + residual ----------------
__global__ void __launch_bounds__(256) k_gcn(const int* __restrict__ ei, int E,
                      const float* __restrict__ eattr, const float* __restrict__ ew,
                      const float* __restrict__ gg, const float* __restrict__ gb,
                      const float* __restrict__ emb, const int* __restrict__ root){
    __shared__ float ws[128*7];
    int tid = threadIdx.x;
    for(int i=tid;i<128*7;i+=256) ws[i]=ew[i];
    __syncthreads();

    int warp = tid>>5, lane = tid&31;
    int n = blockIdx.x*8 + warp;
    float dn = g_dis[n];
    float acc[4] = {0.f,0.f,0.f,0.f};
    int beg = g_off[n], end = g_off[n+1];
    int i = beg;
    for(; i+4<=end; i+=4){
        int e0=g_elist[i], e1=g_elist[i+1], e2=g_elist[i+2], e3=g_elist[i+3];
        int r0=ei[e0], r1=ei[e1], r2=ei[e2], r3=ei[e3];
        float en0=g_dis[r0]*dn, en1=g_dis[r1]*dn, en2=g_dis[r2]*dn, en3=g_dis[r3]*dn;
        float v0=(lane<7)?eattr[(size_t)e0*7+lane]:0.f;
        float v1=(lane<7)?eattr[(size_t)e1*7+lane]:0.f;
        float v2=(lane<7)?eattr[(size_t)e2*7+lane]:0.f;
        float v3=(lane<7)?eattr[(size_t)e3*7+lane]:0.f;
        float h0[4],h1[4],h2[4],h3[4];
#pragma unroll
        for(int c=0;c<4;c++){
            int f = c*32 + lane;
            h0[c]=g_h[(size_t)r0*Ff+f];
            h1[c]=g_h[(size_t)r1*Ff+f];
            h2[c]=g_h[(size_t)r2*Ff+f];
            h3[c]=g_h[(size_t)r3*Ff+f];
        }
        float ea[7];
#pragma unroll
        for(int j=0;j<7;j++) ea[j]=__shfl_sync(0xffffffffu,v0,j);
#pragma unroll
        for(int c=0;c<4;c++){ int f=c*32+lane; float s=h0[c]; const float* w=&ws[f*7];
#pragma unroll
            for(int j=0;j<7;j++) s+=ea[j]*w[j]; acc[c]+=fmaxf(s,0.f)*en0; }
#pragma unroll
        for(int j=0;j<7;j++) ea[j]=__shfl_sync(0xffffffffu,v1,j);
#pragma unroll
        for(int c=0;c<4;c++){ int f=c*32+lane; float s=h1[c]; const float* w=&ws[f*7];
#pragma unroll
            for(int j=0;j<7;j++) s+=ea[j]*w[j]; acc[c]+=fmaxf(s,0.f)*en1; }
#pragma unroll
        for(int j=0;j<7;j++) ea[j]=__shfl_sync(0xffffffffu,v2,j);
#pragma unroll
        for(int c=0;c<4;c++){ int f=c*32+lane; float s=h2[c]; const float* w=&ws[f*7];
#pragma unroll
            for(int j=0;j<7;j++) s+=ea[j]*w[j]; acc[c]+=fmaxf(s,0.f)*en2; }
#pragma unroll
        for(int j=0;j<7;j++) ea[j]=__shfl_sync(0xffffffffu,v3,j);
#pragma unroll
        for(int c=0;c<4;c++){ int f=c*32+lane; float s=h3[c]; const float* w=&ws[f*7];
#pragma unroll
            for(int j=0;j<7;j++) s+=ea[j]*w[j]; acc[c]+=fmaxf(s,0.f)*en3; }
    }
    for(; i<end; i++){
        int e = g_elist[i];
        int row = ei[e];
        float en = g_dis[row]*dn;
        float eav = (lane<7) ? eattr[(size_t)e*7+lane] : 0.f;
        float ea[7];
#pragma unroll
        for(int j=0;j<7;j++) ea[j] = __shfl_sync(0xffffffffu, eav, j);
#pragma unroll
        for(int c=0;c<4;c++){
            int f = c*32 + lane;
            float s = g_h[(size_t)row*Ff + f];
            const float* w = &ws[f*7];
#pragma unroll
            for(int j=0;j<7;j++) s += ea[j]*w[j];
            acc[c] += fmaxf(s, 0.f)*en;
        }
    }
    float dvinv = dn*dn;
    const float* er = emb + root[n]*Ff;
    float t[4]; float s=0.f;
#pragma unroll
    for(int c=0;c<4;c++){
        int f = c*32 + lane;
        float hv = g_h[(size_t)n*Ff+f] + er[f];
        t[c] = acc[c] + fmaxf(hv,0.f)*dvinv;
        s += t[c];
    }
    float mean = warpsum(s) * (1.f/Ff);
    float vv=0.f;
#pragma unroll
    for(int c=0;c<4;c++){ float d=t[c]-mean; vv += d*d; }
    float inv = rsqrtf(warpsum(vv)*(1.f/Ff) + 1e-5f);
#pragma unroll
    for(int c=0;c<4;c++){
        int f = c*32 + lane;
        float y = (t[c]-mean)*inv*gg[f] + gb[f];
        g_out[(size_t)n*Ff+f] += fmaxf(y, 0.f);
    }
}

// ---------------- residual + layernorm (final only) ----------------
__global__ void k_addln(const float* __restrict__ a, const float* __restrict__ res,
                        const float* __restrict__ gg, const float* __restrict__ gb,
                        float* __restrict__ out){
    int warp = threadIdx.x>>5, lane = threadIdx.x&31;
    int n = blockIdx.x*8 + warp;
    float t[4]; float s=0;
#pragma unroll
    for(int c=0;c<4;c++){
        int f = c*32 + lane;
        float v = a[(size_t)n*Ff+f];
        if(res) v += res[(size_t)n*Ff+f];
        t[c]=v; s+=v;
    }
    float mean = warpsum(s) * (1.f/Ff);
    float vv=0;
#pragma unroll
    for(int c=0;c<4;c++){ float d=t[c]-mean; vv += d*d; }
    float inv = rsqrtf(warpsum(vv)*(1.f/Ff) + 1e-5f);
#pragma unroll
    for(int c=0;c<4;c++){
        int f = c*32 + lane;
        out[(size_t)n*Ff+f] = (t[c]-mean)*inv*gg[f] + gb[f];
    }
}

// ---------------- fused attention: packed f32x2, 4-wide m unroll ----------------
__global__ void __launch_bounds__(256) k_attn(const float* __restrict__ mclw, const int* __restrict__ n_counts){
    int h = blockIdx.x, b = blockIdx.y;
    __shared__ __align__(16) float ks[Nn][DHh];
    __shared__ __align__(16) float vs[Nn][DHh];
    int tid = threadIdx.x;

#pragma unroll
    for(int c=0;c<4;c++){
        *(float4*)&ks[tid][c*4] = *(const float4*)(g_k + ((size_t)(b*Nn+tid)*Ff) + h*DHh + c*4);
        *(float4*)&vs[tid][c*4] = *(const float4*)(g_v + ((size_t)(b*Nn+tid)*Ff) + h*DHh + c*4);
    }
    __syncthreads();

    int n  = tid;
    int nc = n_counts[b];
    bool vn = (n < nc);
    float w = mclw[h];
    const float* mrow = g_r + ((size_t)(b*Nn+n))*Nn;

    unsigned long long q2[8];
    {
        const unsigned long long* qp =
            (const unsigned long long*)(g_q + ((size_t)(b*Nn+n))*Ff + h*DHh);
#pragma unroll
        for(int j=0;j<8;j++) q2[j] = qp[j];
    }
    unsigned long long acc2[8];
#pragma unroll
    for(int j=0;j<8;j++) acc2[j] = 0ull;

    float mx = -1e30f, sum = 0.f;
    for(int m=0;m<Nn;m+=4){
        float s4[4];
#pragma unroll
        for(int r=0;r<4;r++){
            const unsigned long long* kp = (const unsigned long long*)&ks[m+r][0];
            unsigned long long t = 0ull;
#pragma unroll
            for(int j=0;j<8;j++) t = fma2(q2[j], kp[j], t);
            float lo, hi; unpack2(t, lo, hi);
            s4[r] = lo + hi;
        }
        float4 mr = *(const float4*)(mrow + m);
        s4[0] += ((vn && (m  <nc)) ? 0.f : -1024.f) + mr.x*w;
        s4[1] += ((vn && (m+1<nc)) ? 0.f : -1024.f) + mr.y*w;
        s4[2] += ((vn && (m+2<nc)) ? 0.f : -1024.f) + mr.z*w;
        s4[3] += ((vn && (m+3<nc)) ? 0.f : -1024.f) + mr.w*w;

        float gmax = fmaxf(fmaxf(s4[0],s4[1]), fmaxf(s4[2],s4[3]));
        if(gmax > mx){
            float sc = __expf(mx - gmax);
            sum *= sc;
            unsigned long long sc2 = pack2(sc, sc);
#pragma unroll
            for(int j=0;j<8;j++) acc2[j] = mul2(acc2[j], sc2);
            mx = gmax;
        }
#pragma unroll
        for(int r=0;r<4;r++){
            float p = __expf(s4[r] - mx);
            sum += p;
            unsigned long long pp = pack2(p, p);
            const unsigned long long* vp = (const unsigned long long*)&vs[m+r][0];
#pragma unroll
            for(int j=0;j<8;j++) acc2[j] = fma2(vp[j], pp, acc2[j]);
        }
    }
    float inv = 1.f/sum;
    float* op = g_o + ((size_t)(b*Nn+n))*Ff + h*DHh;
#pragma unroll
    for(int j=0;j<8;j++){
        float lo, hi; unpack2(acc2[j], lo, hi);
        op[2*j]   = lo*inv;
        op[2*j+1] = hi*inv;
    }
}

// ---------------- host ----------------
extern "C" void kernel_launch(void* const* d_in, const int* in_sizes, int n_in,
                              void* d_out, int out_size){
    (void)n_in; (void)out_size;
    const float* input_x      = (const float*)d_in[0];
    const float* edge_attr    = (const float*)d_in[1];
    const float* gcn_lin_w    = (const float*)d_in[2];
    const float* gcn_root_emb = (const float*)d_in[3];
    const float* gcn_edge_w   = (const float*)d_in[4];
    const float* gcn_norm_g   = (const float*)d_in[5];
    const float* gcn_norm_b   = (const float*)d_in[6];
    const float* ln_in_g      = (const float*)d_in[7];
    const float* ln_in_b      = (const float*)d_in[8];
    const float* ln_ffn_g     = (const float*)d_in[9];
    const float* ln_ffn_b     = (const float*)d_in[10];
    const float* mcl_w        = (const float*)d_in[11];
    const float* q_w          = (const float*)d_in[12];
    const float* k_w          = (const float*)d_in[13];
    const float* v_w          = (const float*)d_in[14];
    const float* merge_w      = (const float*)d_in[15];
    const float* merge_b      = (const float*)d_in[16];
    const float* ffn_w1       = (const float*)d_in[17];
    const float* ffn_b1       = (const float*)d_in[18];
    const float* ffn_w2       = (const float*)d_in[19];
    const float* ffn_b2       = (const float*)d_in[20];
    const float* final_g      = (const float*)d_in[21];
    const float* final_b      = (const float*)d_in[22];
    const int*   edge_index   = (const int*)d_in[23];
    const int*   n_counts     = (const int*)d_in[24];
    const int*   root         = (const int*)d_in[25];
    int E = in_sizes[23] / 2;

    float *m_p,*r_p,*out_p,*h_p,*o_p,*x_p,*f1_p;
    uint32_t *bth0,*btl0,*bth1,*btl1;
    cudaGetSymbolAddress((void**)&m_p,   g_m);
    cudaGetSymbolAddress((void**)&r_p,   g_r);
    cudaGetSymbolAddress((void**)&out_p, g_out);
    cudaGetSymbolAddress((void**)&h_p,   g_h);
    cudaGetSymbolAddress((void**)&o_p,   g_o);
    cudaGetSymbolAddress((void**)&x_p,   g_x);
    cudaGetSymbolAddress((void**)&f1_p,  g_f1);
    cudaGetSymbolAddress((void**)&bth0,  g_bth0);
    cudaGetSymbolAddress((void**)&btl0,  g_btl0);
    cudaGetSymbolAddress((void**)&bth1,  g_bth1);
    cudaGetSymbolAddress((void**)&btl1,  g_btl1);

    // ---- adjacency + MCL ----
    k_init_m<<<(Bb*Nn*Nn+255)/256,256>>>(n_counts);
    k_build_adj<<<(E+255)/256,256>>>(edge_index, E);
    k_rownorm<<<Bb*Nn/8,256>>>(m_p, m_p, 0);
    k_prep_b<<<dim3(8,Bb),256>>>(m_p, bth0, btl0);
    for(int i=0;i<6;i++){
        uint32_t *rh = (i&1)?bth1:bth0, *rl = (i&1)?btl1:btl0;
        uint32_t *wh = (i&1)?bth0:bth1, *wl = (i&1)?btl0:btl1;
        k_bmm_rn<<<dim3(8,Bb),256>>>(m_p, rh, rl, wh, wl,
                                     (i==5)? r_p : nullptr, ((i+1)%3==0)?1:0);
    }

    // ---- degree + csr count / scan(+dis) / scatter ----
    k_zero2<<<(BNn+255)/256,256>>>();
    k_edge_cnt<<<(E+255)/256,256>>>(edge_index, E);
    k_csr_scan<<<1,1024>>>();
    k_csr_scatter<<<(E+255)/256,256>>>(edge_index, E);

    // ---- out = input ----
    cudaMemcpyAsync(out_p, input_x, (size_t)BNn*Ff*sizeof(float), cudaMemcpyDeviceToDevice, 0);

    dim3 g128(Ff/64, BNn/64);        // (2,64)
    dim3 g256(2*Ff/64, BNn/64);      // (4,64)
    dim3 gqkv(Ff/64, BNn/64, 3);     // (2,64,3)

    for(int l=0;l<Ll;l++){
        // ---- GCN ----
        k_gemm_tc<0><<<g128,128>>>(out_p, gcn_lin_w + (size_t)l*Ff*Ff, nullptr, h_p, Ff, Ff, 1.f);
        k_gcn<<<BNn/8,256>>>(edge_index, E, edge_attr, gcn_edge_w + (size_t)l*Ff*7,
                             gcn_norm_g + l*Ff, gcn_norm_b + l*Ff,
                             gcn_root_emb + (size_t)l*2*Ff, root);

        // ---- attention ----
        k_qkv_tc<<<gqkv,128>>>(out_p, q_w + (size_t)l*Ff*Ff, k_w + (size_t)l*Ff*Ff, v_w + (size_t)l*Ff*Ff);
        k_attn<<<dim3(Hh,Bb),256>>>(mcl_w + l*Hh, n_counts);
        k_gemm_ln<<<BNn/32,128>>>(o_p, merge_w + (size_t)l*Ff*Ff, merge_b + l*Ff,
                                  out_p, ln_in_g + l*Ff, ln_in_b + l*Ff, x_p, Ff);

        // ---- FFN ----
        k_gemm_tc<1><<<g256,128>>>(x_p, ffn_w1 + (size_t)l*2*Ff*Ff, ffn_b1 + (size_t)l*2*Ff,
                                   f1_p, 2*Ff, Ff, 1.f);
        k_gemm_ln<<<BNn/32,128>>>(f1_p, ffn_w2 + (size_t)l*Ff*2*Ff, ffn_b2 + l*Ff,
                                  x_p, ln_ffn_g + l*Ff, ln_ffn_b + l*Ff, out_p, 2*Ff);
    }

    // ---- final layernorm ----
    k_addln<<<BNn/8,256>>>(out_p, nullptr, final_g, final_b, (float*)d_out);
}

// round 14
// speedup vs baseline: 1.1208x; 1.1208x over previous
#include <cuda_runtime.h>
#include <cuda_bf16.h>
#include <math.h>
#include <stdint.h>

#define Bb   16
#define Nn   256
#define Ff   128
#define Hh   8
#define DHh  16
#define Ll   9
#define BNn  4096
#define Emax 65536

// ---------------- scratch (device globals; no allocations) ----------------
__device__ float g_m[Bb*Nn*Nn];
__device__ float g_r[Bb*Nn*Nn];
__device__ float g_t[Bb*Nn*Nn];
__device__ float g_deg[BNn];
__device__ float g_dis[BNn];
__device__ float g_out[BNn*Ff];
__device__ float g_h[BNn*Ff];
__device__ float g_q[BNn*Ff];
__device__ float g_k[BNn*Ff];
__device__ float g_v[BNn*Ff];
__device__ float g_o[BNn*Ff];
__device__ float g_x[BNn*Ff];
__device__ float g_f1[BNn*2*Ff];
// CSR by col
__device__ int g_cnt[BNn];
__device__ int g_off[BNn+1];
__device__ int g_cur[BNn];
__device__ int g_elist[Emax];

__device__ __forceinline__ float warpsum(float v){
#pragma unroll
    for(int o=16;o;o>>=1) v += __shfl_xor_sync(0xffffffffu, v, o);
    return v;
}

__device__ __forceinline__ float gelu_exact(float x){
    return 0.5f*x*(1.0f + erff(x*0.70710678118654752f));
}

// ---------------- packed f32x2 helpers (Blackwell FFMA2) ----------------
__device__ __forceinline__ unsigned long long pack2(float lo, float hi){
    unsigned long long r; asm("mov.b64 %0, {%1,%2};" : "=l"(r) : "f"(lo), "f"(hi)); return r;
}
__device__ __forceinline__ void unpack2(unsigned long long v, float& lo, float& hi){
    asm("mov.b64 {%0,%1}, %2;" : "=f"(lo), "=f"(hi) : "l"(v));
}
__device__ __forceinline__ unsigned long long fma2(unsigned long long a, unsigned long long b, unsigned long long c){
    unsigned long long d; asm("fma.rn.f32x2 %0, %1, %2, %3;" : "=l"(d) : "l"(a), "l"(b), "l"(c)); return d;
}
__device__ __forceinline__ unsigned long long mul2(unsigned long long a, unsigned long long b){
    unsigned long long d; asm("mul.rn.f32x2 %0, %1, %2;" : "=l"(d) : "l"(a), "l"(b)); return d;
}

// ---------------- bf16x3 tensor-core GEMM machinery ----------------
// split a pair of consecutive-k floats into packed bf16x2 (hi) + packed bf16x2 (lo).
// Packed converts: cvt.rn.bf16x2.f32 is a single instruction; identical numerics
// to the scalar version (same rn conversions, exact residual subtraction).
__device__ __forceinline__ void splitb(float x, float y, uint32_t& hi, uint32_t& lo){
    __nv_bfloat162 h2 = __floats2bfloat162_rn(x, y);     // low=bf16(x), high=bf16(y)
    float2 hf = __bfloat1622float2(h2);
    __nv_bfloat162 l2 = __floats2bfloat162_rn(x - hf.x, y - hf.y);
    hi = *reinterpret_cast<uint32_t*>(&h2);
    lo = *reinterpret_cast<uint32_t*>(&l2);
}
__device__ __forceinline__ int swz(int r, int k){
    return ((r>>1)<<5) + ((r&1)<<4) + (k ^ (((r>>1)&3)<<2));
}
__device__ __forceinline__ void mma_bf16(float* c, uint32_t a0,uint32_t a1,uint32_t a2,uint32_t a3,
                                         uint32_t b0,uint32_t b1){
    asm volatile("mma.sync.aligned.m16n8k16.row.col.f32.bf16.bf16.f32 "
        "{%0,%1,%2,%3},{%4,%5,%6,%7},{%8,%9},{%0,%1,%2,%3};\n"
        : "+f"(c[0]),"+f"(c[1]),"+f"(c[2]),"+f"(c[3])
        : "r"(a0),"r"(a1),"r"(a2),"r"(a3),"r"(b0),"r"(b1));
}

// C[64x64 tile] = act(alpha * A[M,K] @ W[Nc,K]^T + bias).  128 threads, 4 warps of 32x32.
template<int ACT>
__device__ __forceinline__ void gemm_tc_tile(const float* __restrict__ A, const float* __restrict__ W,
        const float* __restrict__ bias, float* __restrict__ C,
        int Nc, int K, float alpha, int bx, int by)
{
    __shared__ __align__(16) uint32_t As[2][64*16];
    __shared__ __align__(16) uint32_t Ws[2][64*16];
    int tid = threadIdx.x;
    int wid = tid>>5, lane = tid&31, gid = lane>>2, tig = lane&3;
    int wm = (wid&1)*32, wn = (wid>>1)*32;
    int row0 = by*64, col0 = bx*64;
    int lr = tid>>2;
    int lk8 = (tid&3)*8;
    int lw  = (tid&3)*4;

    float acc[2][4][4];
#pragma unroll
    for(int i=0;i<2;i++)
#pragma unroll
    for(int j=0;j<4;j++)
#pragma unroll
    for(int t=0;t<4;t++) acc[i][j][t]=0.f;

    const float* Ap = A + (size_t)(row0+lr)*K + lk8;
    const float* Wp = W + (size_t)(col0+lr)*K + lk8;
    float4 pa0a = *(const float4*)(Ap);
    float4 pa0b = *(const float4*)(Ap+4);
    float4 pa1a = *(const float4*)(Ap + (size_t)32*K);
    float4 pa1b = *(const float4*)(Ap + (size_t)32*K + 4);
    float4 pw0a = *(const float4*)(Wp);
    float4 pw0b = *(const float4*)(Wp+4);
    float4 pw1a = *(const float4*)(Wp + (size_t)32*K);
    float4 pw1b = *(const float4*)(Wp + (size_t)32*K + 4);

    for(int k0=0;k0<K;k0+=32){
        uint4 h, l;
        splitb(pa0a.x,pa0a.y,h.x,l.x); splitb(pa0a.z,pa0a.w,h.y,l.y);
        splitb(pa0b.x,pa0b.y,h.z,l.z); splitb(pa0b.z,pa0b.w,h.w,l.w);
        *(uint4*)&As[0][swz(lr,lw)] = h;  *(uint4*)&As[1][swz(lr,lw)] = l;
        splitb(pa1a.x,pa1a.y,h.x,l.x); splitb(pa1a.z,pa1a.w,h.y,l.y);
        splitb(pa1b.x,pa1b.y,h.z,l.z); splitb(pa1b.z,pa1b.w,h.w,l.w);
        *(uint4*)&As[0][swz(lr+32,lw)] = h;  *(uint4*)&As[1][swz(lr+32,lw)] = l;
        splitb(pw0a.x,pw0a.y,h.x,l.x); splitb(pw0a.z,pw0a.w,h.y,l.y);
        splitb(pw0b.x,pw0b.y,h.z,l.z); splitb(pw0b.z,pw0b.w,h.w,l.w);
        *(uint4*)&Ws[0][swz(lr,lw)] = h;  *(uint4*)&Ws[1][swz(lr,lw)] = l;
        splitb(pw1a.x,pw1a.y,h.x,l.x); splitb(pw1a.z,pw1a.w,h.y,l.y);
        splitb(pw1b.x,pw1b.y,h.z,l.z); splitb(pw1b.z,pw1b.w,h.w,l.w);
        *(uint4*)&Ws[0][swz(lr+32,lw)] = h;  *(uint4*)&Ws[1][swz(lr+32,lw)] = l;
        __syncthreads();

        if(k0+32<K){
            pa0a = *(const float4*)(Ap + k0+32);
            pa0b = *(const float4*)(Ap + k0+36);
            pa1a = *(const float4*)(Ap + (size_t)32*K + k0+32);
            pa1b = *(const float4*)(Ap + (size_t)32*K + k0+36);
            pw0a = *(const float4*)(Wp + k0+32);
            pw0b = *(const float4*)(Wp + k0+36);
            pw1a = *(const float4*)(Wp + (size_t)32*K + k0+32);
            pw1b = *(const float4*)(Wp + (size_t)32*K + k0+36);
        }

#pragma unroll
        for(int s=0;s<2;s++){
            int ks = s*8 + tig;
            uint32_t afh[2][4], afl[2][4], bfh[4][2], bfl[4][2];
#pragma unroll
            for(int i=0;i<2;i++){
                int r = wm + 16*i + gid;
                afh[i][0]=As[0][swz(r,  ks)];   afl[i][0]=As[1][swz(r,  ks)];
                afh[i][1]=As[0][swz(r+8,ks)];   afl[i][1]=As[1][swz(r+8,ks)];
                afh[i][2]=As[0][swz(r,  ks+4)]; afl[i][2]=As[1][swz(r,  ks+4)];
                afh[i][3]=As[0][swz(r+8,ks+4)]; afl[i][3]=As[1][swz(r+8,ks+4)];
            }
#pragma unroll
            for(int j=0;j<4;j++){
                int n = wn + 8*j + gid;
                bfh[j][0]=Ws[0][swz(n,ks)];     bfl[j][0]=Ws[1][swz(n,ks)];
                bfh[j][1]=Ws[0][swz(n,ks+4)];   bfl[j][1]=Ws[1][swz(n,ks+4)];
            }
#pragma unroll
            for(int i=0;i<2;i++)
#pragma unroll
            for(int j=0;j<4;j++){
                mma_bf16(acc[i][j], afl[i][0],afl[i][1],afl[i][2],afl[i][3], bfh[j][0],bfh[j][1]);
                mma_bf16(acc[i][j], afh[i][0],afh[i][1],afh[i][2],afh[i][3], bfl[j][0],bfl[j][1]);
                mma_bf16(acc[i][j], afh[i][0],afh[i][1],afh[i][2],afh[i][3], bfh[j][0],bfh[j][1]);
            }
        }
        __syncthreads();
    }

#pragma unroll
    for(int i=0;i<2;i++){
        int rg = row0 + wm + 16*i + gid;
#pragma unroll
        for(int j=0;j<4;j++){
            int cg = col0 + wn + 8*j + tig*2;
            float b0v = bias ? bias[cg]   : 0.f;
            float b1v = bias ? bias[cg+1] : 0.f;
            float v0 = acc[i][j][0]*alpha + b0v;
            float v1 = acc[i][j][1]*alpha + b1v;
            float v2 = acc[i][j][2]*alpha + b0v;
            float v3 = acc[i][j][3]*alpha + b1v;
            if(ACT==1){ v0=gelu_exact(v0); v1=gelu_exact(v1); v2=gelu_exact(v2); v3=gelu_exact(v3); }
            *(float2*)&C[(size_t)rg*Nc + cg]     = make_float2(v0,v1);
            *(float2*)&C[(size_t)(rg+8)*Nc + cg] = make_float2(v2,v3);
        }
    }
}

template<int ACT>
__global__ void __launch_bounds__(128) k_gemm_tc(const float* __restrict__ A, const float* __restrict__ W,
        const float* __restrict__ bias, float* __restrict__ C, int Nc, int K, float alpha){
    gemm_tc_tile<ACT>(A, W, bias, C, Nc, K, alpha, blockIdx.x, blockIdx.y);
}

__global__ void __launch_bounds__(128) k_qkv_tc(const float* __restrict__ A,
        const float* __restrict__ qw, const float* __restrict__ kw, const float* __restrict__ vw){
    const float* W; float* C; float alpha;
    if(blockIdx.z==0){ W=qw; C=g_q; alpha=0.25f; }
    else if(blockIdx.z==1){ W=kw; C=g_k; alpha=1.f; }
    else { W=vw; C=g_v; alpha=1.f; }
    gemm_tc_tile<0>(A, W, nullptr, C, Ff, Ff, alpha, blockIdx.x, blockIdx.y);
}

// -------- fused GEMM(+bias) + residual + LayerNorm ----------
__global__ void __launch_bounds__(128) k_gemm_ln(const float* __restrict__ A, const float* __restrict__ W,
        const float* __restrict__ bias, const float* __restrict__ res,
        const float* __restrict__ gg, const float* __restrict__ gb,
        float* __restrict__ out, int K)
{
    __shared__ __align__(16) uint32_t As[2][32*16];
    __shared__ __align__(16) uint32_t Ws[2][128*16];
    __shared__ float Cs[32][132];
    int tid = threadIdx.x;
    int wid = tid>>5, lane = tid&31, gid = lane>>2, tig = lane&3;
    int wn = wid*32;
    int row0 = blockIdx.x*32;
    int lr = tid>>2;
    int lk8 = (tid&3)*8;
    int lw  = (tid&3)*4;

    float acc[2][4][4];
#pragma unroll
    for(int i=0;i<2;i++)
#pragma unroll
    for(int j=0;j<4;j++)
#pragma unroll
    for(int t=0;t<4;t++) acc[i][j][t]=0.f;

    const float* Ap = A + (size_t)(row0+lr)*K + lk8;
    const float* Wp = W + (size_t)lr*K + lk8;
    float4 paa = *(const float4*)(Ap);
    float4 pab = *(const float4*)(Ap+4);
    float4 pwa[4], pwb[4];
#pragma unroll
    for(int p=0;p<4;p++){
        pwa[p] = *(const float4*)(Wp + (size_t)32*p*K);
        pwb[p] = *(const float4*)(Wp + (size_t)32*p*K + 4);
    }

    for(int k0=0;k0<K;k0+=32){
        uint4 h, l;
        splitb(paa.x,paa.y,h.x,l.x); splitb(paa.z,paa.w,h.y,l.y);
        splitb(pab.x,pab.y,h.z,l.z); splitb(pab.z,pab.w,h.w,l.w);
        *(uint4*)&As[0][swz(lr,lw)] = h;  *(uint4*)&As[1][swz(lr,lw)] = l;
#pragma unroll
        for(int p=0;p<4;p++){
            splitb(pwa[p].x,pwa[p].y,h.x,l.x); splitb(pwa[p].z,pwa[p].w,h.y,l.y);
            splitb(pwb[p].x,pwb[p].y,h.z,l.z); splitb(pwb[p].z,pwb[p].w,h.w,l.w);
            *(uint4*)&Ws[0][swz(lr+32*p,lw)] = h;  *(uint4*)&Ws[1][swz(lr+32*p,lw)] = l;
        }
        __syncthreads();

        if(k0+32<K){
            paa = *(const float4*)(Ap + k0+32);
            pab = *(const float4*)(Ap + k0+36);
#pragma unroll
            for(int p=0;p<4;p++){
                pwa[p] = *(const float4*)(Wp + (size_t)32*p*K + k0+32);
                pwb[p] = *(const float4*)(Wp + (size_t)32*p*K + k0+36);
            }
        }

#pragma unroll
        for(int s=0;s<2;s++){
            int ks = s*8 + tig;
            uint32_t afh[2][4], afl[2][4];
#pragma unroll
            for(int i=0;i<2;i++){
                int r = 16*i + gid;
                afh[i][0]=As[0][swz(r,  ks)];   afl[i][0]=As[1][swz(r,  ks)];
                afh[i][1]=As[0][swz(r+8,ks)];   afl[i][1]=As[1][swz(r+8,ks)];
                afh[i][2]=As[0][swz(r,  ks+4)]; afl[i][2]=As[1][swz(r,  ks+4)];
                afh[i][3]=As[0][swz(r+8,ks+4)]; afl[i][3]=As[1][swz(r+8,ks+4)];
            }
#pragma unroll
            for(int j=0;j<4;j++){
                int n = wn + 8*j + gid;
                uint32_t b0h=Ws[0][swz(n,ks)],   b0l=Ws[1][swz(n,ks)];
                uint32_t b1h=Ws[0][swz(n,ks+4)], b1l=Ws[1][swz(n,ks+4)];
#pragma unroll
                for(int i=0;i<2;i++){
                    mma_bf16(acc[i][j], afl[i][0],afl[i][1],afl[i][2],afl[i][3], b0h,b1h);
                    mma_bf16(acc[i][j], afh[i][0],afh[i][1],afh[i][2],afh[i][3], b0l,b1l);
                    mma_bf16(acc[i][j], afh[i][0],afh[i][1],afh[i][2],afh[i][3], b0h,b1h);
                }
            }
        }
        __syncthreads();
    }

#pragma unroll
    for(int i=0;i<2;i++){
        int rg = 16*i + gid;
#pragma unroll
        for(int j=0;j<4;j++){
            int cg = wn + 8*j + tig*2;
            float b0v = bias[cg], b1v = bias[cg+1];
            *(float2*)&Cs[rg][cg]   = make_float2(acc[i][j][0]+b0v, acc[i][j][1]+b1v);
            *(float2*)&Cs[rg+8][cg] = make_float2(acc[i][j][2]+b0v, acc[i][j][3]+b1v);
        }
    }
    __syncthreads();

    int r = tid>>2, part = tid&3;
    const float* resp = res + (size_t)(row0+r)*Ff + part*32;
    float v[32]; float s=0.f;
#pragma unroll
    for(int i=0;i<8;i++){
        float4 rv = *(const float4*)(resp + i*4);
        float* cp = &Cs[r][part*32 + i*4];
        v[i*4+0]=cp[0]+rv.x; v[i*4+1]=cp[1]+rv.y; v[i*4+2]=cp[2]+rv.z; v[i*4+3]=cp[3]+rv.w;
        s += v[i*4+0]+v[i*4+1]+v[i*4+2]+v[i*4+3];
    }
    s += __shfl_xor_sync(0xffffffffu, s, 1);
    s += __shfl_xor_sync(0xffffffffu, s, 2);
    float mean = s * (1.f/Ff);
    float vv=0.f;
#pragma unroll
    for(int i=0;i<32;i++){ float d=v[i]-mean; vv += d*d; }
    vv += __shfl_xor_sync(0xffffffffu, vv, 1);
    vv += __shfl_xor_sync(0xffffffffu, vv, 2);
    float inv = rsqrtf(vv*(1.f/Ff) + 1e-5f);
    float* op = out + (size_t)(row0+r)*Ff + part*32;
#pragma unroll
    for(int i=0;i<8;i++){
        int c = part*32 + i*4;
        float4 o;
        o.x=(v[i*4+0]-mean)*inv*gg[c]   + gb[c];
        o.y=(v[i*4+1]-mean)*inv*gg[c+1] + gb[c+1];
        o.z=(v[i*4+2]-mean)*inv*gg[c+2] + gb[c+2];
        o.w=(v[i*4+3]-mean)*inv*gg[c+3] + gb[c+3];
        *(float4*)(op + i*4) = o;
    }
}

// ---- MCL step fused: D = rownorm( A @ B [, ^6] ) ----  (R12 proven)
__global__ void __launch_bounds__(256) k_bmm_rn(const float* __restrict__ A, const float* __restrict__ B,
                                                float* __restrict__ D, int pow6){
    int bb = blockIdx.y;
    const float* Ab = A + (size_t)bb*Nn*Nn;
    const float* Bp = B + (size_t)bb*Nn*Nn;
    float*       Dp = D + (size_t)bb*Nn*Nn;

    __shared__ __align__(16) uint32_t SM[2*32*16 + 2*256*16];   // 36KB
    uint32_t (*As)[32*16]  = (uint32_t(*)[32*16])SM;
    uint32_t (*Bs)[256*16] = (uint32_t(*)[256*16])(SM + 2*32*16);
    float (*Cs)[260] = (float(*)[260])SM;

    int tid = threadIdx.x;
    int wid = tid>>5, lane = tid&31, gid = lane>>2, tig = lane&3;
    int wn = wid*32;
    int row0 = blockIdx.x*32;
    int lr4 = tid>>3;
    int lk4 = (tid&7)*4;
    int lkw = (tid&7)*2;

    float acc[2][4][4];
#pragma unroll
    for(int i=0;i<2;i++)
#pragma unroll
    for(int j=0;j<4;j++)
#pragma unroll
    for(int t=0;t<4;t++) acc[i][j][t]=0.f;

    for(int k0=0;k0<Nn;k0+=32){
        {
            float4 a4 = *(const float4*)(Ab + (size_t)(row0+lr4)*Nn + k0+lk4);
            uint32_t h0,l0,h1,l1;
            splitb(a4.x,a4.y,h0,l0); splitb(a4.z,a4.w,h1,l1);
            uint2 hh; hh.x=h0; hh.y=h1;
            uint2 ll; ll.x=l0; ll.y=l1;
            *(uint2*)&As[0][swz(lr4,lkw)] = hh;
            *(uint2*)&As[1][swz(lr4,lkw)] = ll;
        }
        {
            float pb[32];
#pragma unroll
            for(int i=0;i<32;i++) pb[i] = Bp[(size_t)(k0+i)*Nn + tid];
#pragma unroll
            for(int q=0;q<4;q++){
                uint4 h, l;
                splitb(pb[q*8+0],pb[q*8+1],h.x,l.x);
                splitb(pb[q*8+2],pb[q*8+3],h.y,l.y);
                splitb(pb[q*8+4],pb[q*8+5],h.z,l.z);
                splitb(pb[q*8+6],pb[q*8+7],h.w,l.w);
                *(uint4*)&Bs[0][swz(tid, q*4)] = h;
                *(uint4*)&Bs[1][swz(tid, q*4)] = l;
            }
        }
        __syncthreads();

#pragma unroll
        for(int s=0;s<2;s++){
            int ks = s*8 + tig;
            uint32_t afh[2][4], afl[2][4];
#pragma unroll
            for(int i=0;i<2;i++){
                int r = 16*i + gid;
                afh[i][0]=As[0][swz(r,  ks)];   afl[i][0]=As[1][swz(r,  ks)];
                afh[i][1]=As[0][swz(r+8,ks)];   afl[i][1]=As[1][swz(r+8,ks)];
                afh[i][2]=As[0][swz(r,  ks+4)]; afl[i][2]=As[1][swz(r,  ks+4)];
                afh[i][3]=As[0][swz(r+8,ks+4)]; afl[i][3]=As[1][swz(r+8,ks+4)];
            }
#pragma unroll
            for(int j=0;j<4;j++){
                int n = wn + 8*j + gid;
                uint32_t b0h=Bs[0][swz(n,ks)],   b0l=Bs[1][swz(n,ks)];
                uint32_t b1h=Bs[0][swz(n,ks+4)], b1l=Bs[1][swz(n,ks+4)];
#pragma unroll
                for(int i=0;i<2;i++){
                    mma_bf16(acc[i][j], afl[i][0],afl[i][1],afl[i][2],afl[i][3], b0h,b1h);
                    mma_bf16(acc[i][j], afh[i][0],afh[i][1],afh[i][2],afh[i][3], b0l,b1l);
                    mma_bf16(acc[i][j], afh[i][0],afh[i][1],afh[i][2],afh[i][3], b0h,b1h);
                }
            }
        }
        __syncthreads();
    }

#pragma unroll
    for(int i=0;i<2;i++){
        int rg = 16*i + gid;
#pragma unroll
        for(int j=0;j<4;j++){
            int cg = wn + 8*j + tig*2;
            *(float2*)&Cs[rg][cg]   = make_float2(acc[i][j][0], acc[i][j][1]);
            *(float2*)&Cs[rg+8][cg] = make_float2(acc[i][j][2], acc[i][j][3]);
        }
    }
    __syncthreads();

    int r = tid>>3, part = tid&7;
    float s = 0.f;
#pragma unroll
    for(int i=0;i<8;i++){
        float4 c = *(const float4*)&Cs[r][part*4 + i*32];
        if(pow6){
            float t;
            t=c.x*c.x; c.x=t*t*t;  t=c.y*c.y; c.y=t*t*t;
            t=c.z*c.z; c.z=t*t*t;  t=c.w*c.w; c.w=t*t*t;
        }
        s += c.x+c.y+c.z+c.w;
    }
    s += __shfl_xor_sync(0xffffffffu, s, 1);
    s += __shfl_xor_sync(0xffffffffu, s, 2);
    s += __shfl_xor_sync(0xffffffffu, s, 4);
    float inv = 1.0f/(s + 1e-6f);
    float* dp = Dp + (size_t)(row0+r)*Nn;
#pragma unroll
    for(int i=0;i<8;i++){
        float4 c = *(const float4*)&Cs[r][part*4 + i*32];
        if(pow6){
            float t;
            t=c.x*c.x; c.x=t*t*t;  t=c.y*c.y; c.y=t*t*t;
            t=c.z*c.z; c.z=t*t*t;  t=c.w*c.w; c.w=t*t*t;
        }
        c.x*=inv; c.y*=inv; c.z*=inv; c.w*=inv;
        *(float4*)(dp + part*4 + i*32) = c;
    }
}

// ---------------- setup kernels ----------------
__global__ void k_init_m(const int* __restrict__ n_counts){
    int i = blockIdx.x*blockDim.x + threadIdx.x;
    if(i >= Bb*Nn*Nn) return;
    int b = i / (Nn*Nn);
    int rc = i % (Nn*Nn);
    int r = rc / Nn, c = rc % Nn;
    g_m[i] = (r==c && r < n_counts[b]) ? 1.0f : 0.0f;
}

__global__ void k_build_adj(const int* __restrict__ ei, int E){
    int e = blockIdx.x*blockDim.x + threadIdx.x;
    if(e>=E) return;
    int row = ei[e], col = ei[E+e];
    int eb = row/Nn, es = row%Nn, et = col%Nn;
    g_m[(eb*Nn+es)*Nn + et] = 1.0f;
}

__global__ void k_rownorm(const float* __restrict__ src, float* __restrict__ dst, int pow6){
    int warp = threadIdx.x>>5, lane = threadIdx.x&31;
    int row = blockIdx.x*8 + warp;
    const float* sp = src + (size_t)row*Nn + lane*8;
    float4 a = *(const float4*)(sp);
    float4 b = *(const float4*)(sp+4);
    if(pow6){
        float t;
        t=a.x*a.x; a.x=t*t*t;  t=a.y*a.y; a.y=t*t*t;
        t=a.z*a.z; a.z=t*t*t;  t=a.w*a.w; a.w=t*t*t;
        t=b.x*b.x; b.x=t*t*t;  t=b.y*b.y; b.y=t*t*t;
        t=b.z*b.z; b.z=t*t*t;  t=b.w*b.w; b.w=t*t*t;
    }
    float s = a.x+a.y+a.z+a.w + b.x+b.y+b.z+b.w;
    s = warpsum(s);
    float inv = 1.0f/(s + 1e-6f);
    a.x*=inv; a.y*=inv; a.z*=inv; a.w*=inv;
    b.x*=inv; b.y*=inv; b.z*=inv; b.w*=inv;
    float* dp = dst + (size_t)row*Nn + lane*8;
    *(float4*)(dp)   = a;
    *(float4*)(dp+4) = b;
}

__global__ void k_zero2(){
    int i = blockIdx.x*blockDim.x + threadIdx.x;
    if(i<BNn){ g_deg[i]=0.f; g_cnt[i]=0; }
}
__global__ void k_edge_cnt(const int* __restrict__ ei, int E){
    int e = blockIdx.x*blockDim.x + threadIdx.x;
    if(e>=E) return;
    atomicAdd(&g_deg[ei[e]], 1.0f);
    atomicAdd(&g_cnt[ei[E+e]], 1);
}

__global__ void k_csr_scan(){
    __shared__ int wsum[32];
    int tid = threadIdx.x;
    int base = tid*4;
    int v0=g_cnt[base], v1=g_cnt[base+1], v2=g_cnt[base+2], v3=g_cnt[base+3];
    int sum = v0+v1+v2+v3;
    int lane = tid&31, wid = tid>>5;
    int x = sum;
#pragma unroll
    for(int o=1;o<32;o<<=1){ int y=__shfl_up_sync(0xffffffffu,x,o); if(lane>=o) x+=y; }
    if(lane==31) wsum[wid]=x;
    __syncthreads();
    if(wid==0){
        int t = wsum[lane];
#pragma unroll
        for(int o=1;o<32;o<<=1){ int y=__shfl_up_sync(0xffffffffu,t,o); if(lane>=o) t+=y; }
        wsum[lane]=t;
    }
    __syncthreads();
    int excl = x - sum + (wid ? wsum[wid-1] : 0);
    int run = excl;
    g_off[base]=run;   g_cur[base]=run;   run+=v0;
    g_off[base+1]=run; g_cur[base+1]=run; run+=v1;
    g_off[base+2]=run; g_cur[base+2]=run; run+=v2;
    g_off[base+3]=run; g_cur[base+3]=run; run+=v3;
    if(tid==1023) g_off[BNn]=run;
#pragma unroll
    for(int j=0;j<4;j++) g_dis[base+j] = rsqrtf(g_deg[base+j] + 1.0f);
}
__global__ void k_csr_scatter(const int* __restrict__ ei, int E){
    int e = blockIdx.x*blockDim.x + threadIdx.x;
    if(e>=E) return;
    int pos = atomicAdd(&g_cur[ei[E+e]], 1);
    g_elist[pos] = e;
}

// ---------------- fused GCN: gather (CSR, 4-edge batched) + node update + LN + residual ----------------
__global__ void __launch_bounds__(256) k_gcn(const int* __restrict__ ei, int E,
                      const float* __restrict__ eattr, const float* __restrict__ ew,
                      const float* __restrict__ gg, const float* __restrict__ gb,
                      const float* __restrict__ emb, const int* __restrict__ root){
    __shared__ float ws[128*7];
    int tid = threadIdx.x;
    for(int i=tid;i<128*7;i+=256) ws[i]=ew[i];
    __syncthreads();

    int warp = tid>>5, lane = tid&31;
    int n = blockIdx.x*8 + warp;
    float dn = g_dis[n];
    float acc[4] = {0.f,0.f,0.f,0.f};
    int beg = g_off[n], end = g_off[n+1];
    int i = beg;
    for(; i+4<=end; i+=4){
        int e0=g_elist[i], e1=g_elist[i+1], e2=g_elist[i+2], e3=g_elist[i+3];
        int r0=ei[e0], r1=ei[e1], r2=ei[e2], r3=ei[e3];
        float en0=g_dis[r0]*dn, en1=g_dis[r1]*dn, en2=g_dis[r2]*dn, en3=g_dis[r3]*dn;
        float v0=(lane<7)?eattr[(size_t)e0*7+lane]:0.f;
        float v1=(lane<7)?eattr[(size_t)e1*7+lane]:0.f;
        float v2=(lane<7)?eattr[(size_t)e2*7+lane]:0.f;
        float v3=(lane<7)?eattr[(size_t)e3*7+lane]:0.f;
        float h0[4],h1[4],h2[4],h3[4];
#pragma unroll
        for(int c=0;c<4;c++){
            int f = c*32 + lane;
            h0[c]=g_h[(size_t)r0*Ff+f];
            h1[c]=g_h[(size_t)r1*Ff+f];
            h2[c]=g_h[(size_t)r2*Ff+f];
            h3[c]=g_h[(size_t)r3*Ff+f];
        }
        float ea[7];
#pragma unroll
        for(int j=0;j<7;j++) ea[j]=__shfl_sync(0xffffffffu,v0,j);
#pragma unroll
        for(int c=0;c<4;c++){ int f=c*32+lane; float s=h0[c]; const float* w=&ws[f*7];
#pragma unroll
            for(int j=0;j<7;j++) s+=ea[j]*w[j]; acc[c]+=fmaxf(s,0.f)*en0; }
#pragma unroll
        for(int j=0;j<7;j++) ea[j]=__shfl_sync(0xffffffffu,v1,j);
#pragma unroll
        for(int c=0;c<4;c++){ int f=c*32+lane; float s=h1[c]; const float* w=&ws[f*7];
#pragma unroll
            for(int j=0;j<7;j++) s+=ea[j]*w[j]; acc[c]+=fmaxf(s,0.f)*en1; }
#pragma unroll
        for(int j=0;j<7;j++) ea[j]=__shfl_sync(0xffffffffu,v2,j);
#pragma unroll
        for(int c=0;c<4;c++){ int f=c*32+lane; float s=h2[c]; const float* w=&ws[f*7];
#pragma unroll
            for(int j=0;j<7;j++) s+=ea[j]*w[j]; acc[c]+=fmaxf(s,0.f)*en2; }
#pragma unroll
        for(int j=0;j<7;j++) ea[j]=__shfl_sync(0xffffffffu,v3,j);
#pragma unroll
        for(int c=0;c<4;c++){ int f=c*32+lane; float s=h3[c]; const float* w=&ws[f*7];
#pragma unroll
            for(int j=0;j<7;j++) s+=ea[j]*w[j]; acc[c]+=fmaxf(s,0.f)*en3; }
    }
    for(; i<end; i++){
        int e = g_elist[i];
        int row = ei[e];
        float en = g_dis[row]*dn;
        float eav = (lane<7) ? eattr[(size_t)e*7+lane] : 0.f;
        float ea[7];
#pragma unroll
        for(int j=0;j<7;j++) ea[j] = __shfl_sync(0xffffffffu, eav, j);
#pragma unroll
        for(int c=0;c<4;c++){
            int f = c*32 + lane;
            float s = g_h[(size_t)row*Ff + f];
            const float* w = &ws[f*7];
#pragma unroll
            for(int j=0;j<7;j++) s += ea[j]*w[j];
            acc[c] += fmaxf(s, 0.f)*en;
        }
    }
    float dvinv = dn*dn;
    const float* er = emb + root[n]*Ff;
    float t[4]; float s=0.f;
#pragma unroll
    for(int c=0;c<4;c++){
        int f = c*32 + lane;
        float hv = g_h[(size_t)n*Ff+f] + er[f];
        t[c] = acc[c] + fmaxf(hv,0.f)*dvinv;
        s += t[c];
    }
    float mean = warpsum(s) * (1.f/Ff);
    float vv=0.f;
#pragma unroll
    for(int c=0;c<4;c++){ float d=t[c]-mean; vv += d*d; }
    float inv = rsqrtf(warpsum(vv)*(1.f/Ff) + 1e-5f);
#pragma unroll
    for(int c=0;c<4;c++){
        int f = c*32 + lane;
        float y = (t[c]-mean)*inv*gg[f] + gb[f];
        g_out[(size_t)n*Ff+f] += fmaxf(y, 0.f);
    }
}

// ---------------- residual + layernorm (final only) ----------------
__global__ void k_addln(const float* __restrict__ a, const float* __restrict__ res,
                        const float* __restrict__ gg, const float* __restrict__ gb,
                        float* __restrict__ out){
    int warp = threadIdx.x>>5, lane = threadIdx.x&31;
    int n = blockIdx.x*8 + warp;
    float t[4]; float s=0;
#pragma unroll
    for(int c=0;c<4;c++){
        int f = c*32 + lane;
        float v = a[(size_t)n*Ff+f];
        if(res) v += res[(size_t)n*Ff+f];
        t[c]=v; s+=v;
    }
    float mean = warpsum(s) * (1.f/Ff);
    float vv=0;
#pragma unroll
    for(int c=0;c<4;c++){ float d=t[c]-mean; vv += d*d; }
    float inv = rsqrtf(warpsum(vv)*(1.f/Ff) + 1e-5f);
#pragma unroll
    for(int c=0;c<4;c++){
        int f = c*32 + lane;
        out[(size_t)n*Ff+f] = (t[c]-mean)*inv*gg[f] + gb[f];
    }
}

// ---------------- fused attention: packed f32x2, 4-wide m unroll (R8 proven) ----------------
__global__ void __launch_bounds__(256) k_attn(const float* __restrict__ mclw, const int* __restrict__ n_counts){
    int h = blockIdx.x, b = blockIdx.y;
    __shared__ __align__(16) float ks[Nn][DHh];
    __shared__ __align__(16) float vs[Nn][DHh];
    int tid = threadIdx.x;

#pragma unroll
    for(int c=0;c<4;c++){
        *(float4*)&ks[tid][c*4] = *(const float4*)(g_k + ((size_t)(b*Nn+tid)*Ff) + h*DHh + c*4);
        *(float4*)&vs[tid][c*4] = *(const float4*)(g_v + ((size_t)(b*Nn+tid)*Ff) + h*DHh + c*4);
    }
    __syncthreads();

    int n  = tid;
    int nc = n_counts[b];
    bool vn = (n < nc);
    float w = mclw[h];
    const float* mrow = g_r + ((size_t)(b*Nn+n))*Nn;

    unsigned long long q2[8];
    {
        const unsigned long long* qp =
            (const unsigned long long*)(g_q + ((size_t)(b*Nn+n))*Ff + h*DHh);
#pragma unroll
        for(int j=0;j<8;j++) q2[j] = qp[j];
    }
    unsigned long long acc2[8];
#pragma unroll
    for(int j=0;j<8;j++) acc2[j] = 0ull;

    float mx = -1e30f, sum = 0.f;
    for(int m=0;m<Nn;m+=4){
        float s4[4];
#pragma unroll
        for(int r=0;r<4;r++){
            const unsigned long long* kp = (const unsigned long long*)&ks[m+r][0];
            unsigned long long t = 0ull;
#pragma unroll
            for(int j=0;j<8;j++) t = fma2(q2[j], kp[j], t);
            float lo, hi; unpack2(t, lo, hi);
            s4[r] = lo + hi;
        }
        float4 mr = *(const float4*)(mrow + m);
        s4[0] += ((vn && (m  <nc)) ? 0.f : -1024.f) + mr.x*w;
        s4[1] += ((vn && (m+1<nc)) ? 0.f : -1024.f) + mr.y*w;
        s4[2] += ((vn && (m+2<nc)) ? 0.f : -1024.f) + mr.z*w;
        s4[3] += ((vn && (m+3<nc)) ? 0.f : -1024.f) + mr.w*w;

        float gmax = fmaxf(fmaxf(s4[0],s4[1]), fmaxf(s4[2],s4[3]));
        if(gmax > mx){
            float sc = __expf(mx - gmax);
            sum *= sc;
            unsigned long long sc2 = pack2(sc, sc);
#pragma unroll
            for(int j=0;j<8;j++) acc2[j] = mul2(acc2[j], sc2);
            mx = gmax;
        }
#pragma unroll
        for(int r=0;r<4;r++){
            float p = __expf(s4[r] - mx);
            sum += p;
            unsigned long long pp = pack2(p, p);
            const unsigned long long* vp = (const unsigned long long*)&vs[m+r][0];
#pragma unroll
            for(int j=0;j<8;j++) acc2[j] = fma2(vp[j], pp, acc2[j]);
        }
    }
    float inv = 1.f/sum;
    float* op = g_o + ((size_t)(b*Nn+n))*Ff + h*DHh;
#pragma unroll
    for(int j=0;j<8;j++){
        float lo, hi; unpack2(acc2[j], lo, hi);
        op[2*j]   = lo*inv;
        op[2*j+1] = hi*inv;
    }
}

// ---------------- host ----------------
extern "C" void kernel_launch(void* const* d_in, const int* in_sizes, int n_in,
                              void* d_out, int out_size){
    (void)n_in; (void)out_size;
    const float* input_x      = (const float*)d_in[0];
    const float* edge_attr    = (const float*)d_in[1];
    const float* gcn_lin_w    = (const float*)d_in[2];
    const float* gcn_root_emb = (const float*)d_in[3];
    const float* gcn_edge_w   = (const float*)d_in[4];
    const float* gcn_norm_g   = (const float*)d_in[5];
    const float* gcn_norm_b   = (const float*)d_in[6];
    const float* ln_in_g      = (const float*)d_in[7];
    const float* ln_in_b      = (const float*)d_in[8];
    const float* ln_ffn_g     = (const float*)d_in[9];
    const float* ln_ffn_b     = (const float*)d_in[10];
    const float* mcl_w        = (const float*)d_in[11];
    const float* q_w          = (const float*)d_in[12];
    const float* k_w          = (const float*)d_in[13];
    const float* v_w          = (const float*)d_in[14];
    const float* merge_w      = (const float*)d_in[15];
    const float* merge_b      = (const float*)d_in[16];
    const float* ffn_w1       = (const float*)d_in[17];
    const float* ffn_b1       = (const float*)d_in[18];
    const float* ffn_w2       = (const float*)d_in[19];
    const float* ffn_b2       = (const float*)d_in[20];
    const float* final_g      = (const float*)d_in[21];
    const float* final_b      = (const float*)d_in[22];
    const int*   edge_index   = (const int*)d_in[23];
    const int*   n_counts     = (const int*)d_in[24];
    const int*   root         = (const int*)d_in[25];
    int E = in_sizes[23] / 2;

    float *m_p,*r_p,*t_p,*out_p,*h_p,*o_p,*x_p,*f1_p;
    cudaGetSymbolAddress((void**)&m_p,   g_m);
    cudaGetSymbolAddress((void**)&r_p,   g_r);
    cudaGetSymbolAddress((void**)&t_p,   g_t);
    cudaGetSymbolAddress((void**)&out_p, g_out);
    cudaGetSymbolAddress((void**)&h_p,   g_h);
    cudaGetSymbolAddress((void**)&o_p,   g_o);
    cudaGetSymbolAddress((void**)&x_p,   g_x);
    cudaGetSymbolAddress((void**)&f1_p,  g_f1);

    // ---- adjacency + MCL ----
    k_init_m<<<(Bb*Nn*Nn+255)/256,256>>>(n_counts);
    k_build_adj<<<(E+255)/256,256>>>(edge_index, E);
    k_rownorm<<<Bb*Nn/8,256>>>(m_p, m_p, 0);
    const float* rcur = m_p;
    for(int i=0;i<6;i++){
        float* dst = (i&1) ? r_p : t_p;
        k_bmm_rn<<<dim3(8,Bb),256>>>(m_p, rcur, dst, ((i+1)%3==0)?1:0);
        rcur = dst;
    }
    // final mcl in g_r (i=5 -> r_p)

    // ---- degree + csr count / scan(+dis) / scatter ----
    k_zero2<<<(BNn+255)/256,256>>>();
    k_edge_cnt<<<(E+255)/256,256>>>(edge_index, E);
    k_csr_scan<<<1,1024>>>();
    k_csr_scatter<<<(E+255)/256,256>>>(edge_index, E);

    // ---- out = input ----
    cudaMemcpyAsync(out_p, input_x, (size_t)BNn*Ff*sizeof(float), cudaMemcpyDeviceToDevice, 0);

    dim3 g128(Ff/64, BNn/64);        // (2,64)
    dim3 g256(2*Ff/64, BNn/64);      // (4,64)
    dim3 gqkv(Ff/64, BNn/64, 3);     // (2,64,3)

    for(int l=0;l<Ll;l++){
        // ---- GCN ----
        k_gemm_tc<0><<<g128,128>>>(out_p, gcn_lin_w + (size_t)l*Ff*Ff, nullptr, h_p, Ff, Ff, 1.f);
        k_gcn<<<BNn/8,256>>>(edge_index, E, edge_attr, gcn_edge_w + (size_t)l*Ff*7,
                             gcn_norm_g + l*Ff, gcn_norm_b + l*Ff,
                             gcn_root_emb + (size_t)l*2*Ff, root);

        // ---- attention ----
        k_qkv_tc<<<gqkv,128>>>(out_p, q_w + (size_t)l*Ff*Ff, k_w + (size_t)l*Ff*Ff, v_w + (size_t)l*Ff*Ff);
        k_attn<<<dim3(Hh,Bb),256>>>(mcl_w + l*Hh, n_counts);
        k_gemm_ln<<<BNn/32,128>>>(o_p, merge_w + (size_t)l*Ff*Ff, merge_b + l*Ff,
                                  out_p, ln_in_g + l*Ff, ln_in_b + l*Ff, x_p, Ff);

        // ---- FFN ----
        k_gemm_tc<1><<<g256,128>>>(x_p, ffn_w1 + (size_t)l*2*Ff*Ff, ffn_b1 + (size_t)l*2*Ff,
                                   f1_p, 2*Ff, Ff, 1.f);
        k_gemm_ln<<<BNn/32,128>>>(f1_p, ffn_w2 + (size_t)l*Ff*2*Ff, ffn_b2 + l*Ff,
                                  x_p, ln_ffn_g + l*Ff, ln_ffn_b + l*Ff, out_p, 2*Ff);
    }

    // ---- final layernorm ----
    k_addln<<<BNn/8,256>>>(out_p, nullptr, final_g, final_b, (float*)d_out);
}